// round 10
// baseline (speedup 1.0000x reference)
#include <cuda_runtime.h>
#include <math.h>

// Problem constants
#define NB 32     // batch
#define SS 12     // seq len
#define FF 128    // features
#define KH 8      // heads
#define HH 64     // head dim
#define CC 64     // out channels
#define NN 512    // nodes
#define SEGS 16   // n-segments for Wf reduction (512/16 = 32 rows/segment)

#define FEAT_BLOCKS NB                    // 32 feature blocks FIRST (overlap with stream)
#define WF_BLOCKS (CC * SEGS)             // 1024 stream blocks
#define TOTAL_BLOCKS (FEAT_BLOCKS + WF_BLOCKS)   // 1056
#define FIN_BLOCKS CC                     // 64 finale blocks (one c2 each)
#define FIN_START (TOTAL_BLOCKS - FIN_BLOCKS)    // tickets >= 992 do finale

// Scratch (no allocations allowed)
__device__ float g_v[NB * CC];              // per-batch feature vector v[b][c]
__device__ float g_wfpart[CC * SEGS * CC];  // partials, layout [c2][seg][c]
__device__ unsigned int g_done;             // arrival tickets (zero-init)
__device__ unsigned int g_flag;             // "all arrived" flag
__device__ unsigned int g_fin;              // finale completion counter

// Shared union: stream 1024 | feature 2944 | finale 1024+2048+64=3136 floats
#define SBUF_FLOATS 3136

__global__ void __launch_bounds__(256) kAll(
    const float* __restrict__ Wf,
    const float* __restrict__ x,
    const float* __restrict__ W_heads,
    const float* __restrict__ W_out,
    const float* __restrict__ bf,
    float* __restrict__ out)
{
    __shared__ __align__(16) float sbuf[SBUF_FLOATS];
    int bid = blockIdx.x;
    int tid = threadIdx.x;

    if (bid >= FEAT_BLOCKS) {
        // ---------------- Wf segment reduction (R7 verbatim) ----------------
        int wb  = bid - FEAT_BLOCKS;
        int c2  = wb >> 4;           // 0..63
        int seg = wb & 15;           // 0..15
        int lane = tid & 15;         // float4 index within 64-float row
        int np   = tid >> 4;         // 16 n-partitions, 2 rows each

        const float4* base = (const float4*)(Wf + (size_t)c2 * (NN * CC));

        float4 acc;
        {
            int n0 = seg * 32 + np * 2;
            float4 v0 = base[(n0 + 0) * 16 + lane];
            float4 v1 = base[(n0 + 1) * 16 + lane];
            acc.x = v0.x + v1.x; acc.y = v0.y + v1.y;
            acc.z = v0.z + v1.z; acc.w = v0.w + v1.w;
        }

        float4* sred = (float4*)sbuf;
        sred[tid] = acc;
        __syncthreads();
        #pragma unroll
        for (int s = 8; s >= 1; s >>= 1) {
            if (np < s) {
                float4 o = sred[(np + s) * 16 + lane];
                float4 m = sred[np * 16 + lane];
                m.x += o.x; m.y += o.y; m.z += o.z; m.w += o.w;
                sred[np * 16 + lane] = m;
            }
            __syncthreads();
        }
        if (tid < 16) {
            ((float4*)(g_wfpart + ((size_t)c2 * SEGS + seg) * CC))[lane] = sred[lane];
        }
    } else {
        // ---------------- per-batch feature vector (R7 verbatim) -------------
        int b = bid;

        float* xl    = sbuf;                 // 128
        float* hpart = sbuf + 128;           // [4 fparts][512 j]
        float* hp    = sbuf + 128 + 2048;    // 512
        float* red   = sbuf + 128 + 2048 + 512; // 256

        if (tid < 32)
            ((float4*)xl)[tid] = ((const float4*)(x + b * SS * FF + (SS - 1) * FF))[tid];
        __syncthreads();

        #pragma unroll
        for (int s = 0; s < 2; ++s) {
            int slot  = tid + s * 256;       // 0..511
            int fpart = slot >> 7;           // 0..3
            int jq    = slot & 127;          // j-quad
            int k     = jq >> 4;             // head index
            int h0    = (jq & 15) * 4;
            const float4* w = (const float4*)(W_heads + (size_t)k * FF * HH + h0);
            int f0 = fpart * 32;
            float4 acc = make_float4(0.f, 0.f, 0.f, 0.f);
            #pragma unroll 8
            for (int i = 0; i < 32; ++i) {
                float4 wv = w[(f0 + i) * 16];
                float xv = xl[f0 + i];
                acc.x = fmaf(xv, wv.x, acc.x);
                acc.y = fmaf(xv, wv.y, acc.y);
                acc.z = fmaf(xv, wv.z, acc.z);
                acc.w = fmaf(xv, wv.w, acc.w);
            }
            ((float4*)hpart)[fpart * 128 + jq] = acc;
        }
        __syncthreads();

        #pragma unroll
        for (int s = 0; s < 2; ++s) {
            int j = tid + s * 256;
            float sum = (hpart[j] + hpart[512 + j]) + (hpart[1024 + j] + hpart[1536 + j]);
            hp[j] = (sum > 0.f) ? sum : expm1f(sum);   // elu (alpha=1)
        }
        __syncthreads();

        {
            int c = tid & 63;
            int part = tid >> 6;
            int j0 = part * 128;
            float acc0 = 0.f, acc1 = 0.f;
            #pragma unroll 16
            for (int j = 0; j < 64; ++j) {
                acc0 = fmaf(hp[j0 + j],      W_out[(j0 + j) * CC + c],      acc0);
                acc1 = fmaf(hp[j0 + 64 + j], W_out[(j0 + 64 + j) * CC + c], acc1);
            }
            red[part * 64 + c] = acc0 + acc1;
        }
        __syncthreads();
        #pragma unroll
        for (int s = 2; s >= 1; s >>= 1) {
            int c = tid & 63;
            int part = tid >> 6;
            if (part < s) red[part * 64 + c] += red[(part + s) * 64 + c];
            __syncthreads();
        }
        if (tid < CC) g_v[b * CC + tid] = red[tid];
    }

    // ---------------- ticketed tail: last 64 arrivals do the finale ----------
    __shared__ unsigned int s_ticket;
    __threadfence();                 // release this block's global writes
    __syncthreads();                 // all threads' stores done before arrive
    if (tid == 0) {
        unsigned int t = atomicAdd(&g_done, 1u);
        s_ticket = t;
        if (t == TOTAL_BLOCKS - 1) {         // everyone has arrived (and fenced)
            atomicExch(&g_flag, 1u);
        }
    }
    __syncthreads();
    unsigned int ticket = s_ticket;
    if (ticket < FIN_START) return;

    // wait until ALL blocks' data is globally visible
    if (tid == 0) {
        while (atomicAdd(&g_flag, 0u) == 0u) { }
    }
    __syncthreads();
    __threadfence();                 // acquire

    // ---------------- finale: one c2 per block ----------------
    int c2 = (int)(ticket - FIN_START);

    float* swred = sbuf;             // 1024 (16 segs x 16 float4)
    float* sv    = sbuf + 1024;      // 2048 (all v)
    float* sw    = sbuf + 3072;      // 64

    // partial row for this c2: 256 float4, 1 per thread (contiguous, L2-hot)
    const float4* row4 = (const float4*)(g_wfpart + (size_t)c2 * SEGS * CC);
    float4 pr = row4[tid];
    // all v: 512 float4, 2 per thread
    const float4* gv4 = (const float4*)g_v;
    float4 va = gv4[tid];
    float4 vb = gv4[tid + 256];
    float bias = bf[c2];

    ((float4*)swred)[tid] = pr;
    ((float4*)sv)[tid]        = va;
    ((float4*)sv)[tid + 256]  = vb;
    __syncthreads();

    // sw[c] = sum over 16 segs (64 threads, one per c)
    if (tid < CC) {
        float w = 0.f;
        #pragma unroll
        for (int s = 0; s < SEGS; ++s)
            w += swred[s * CC + tid];
        sw[tid] = w;
    }
    __syncthreads();

    // out[b][c2] = bias + dot(v[b], sw); tid -> b = tid/8, part = tid%8 (8 c's)
    {
        int b = tid >> 3;
        int part = tid & 7;
        const float* svb = sv + b * CC + part * 8;
        const float* swp = sw + part * 8;
        float acc = 0.f;
        #pragma unroll
        for (int c = 0; c < 8; ++c)
            acc = fmaf(svb[c], swp[c], acc);
        acc += __shfl_xor_sync(0xffffffffu, acc, 1);
        acc += __shfl_xor_sync(0xffffffffu, acc, 2);
        acc += __shfl_xor_sync(0xffffffffu, acc, 4);
        if (part == 0)
            out[b * CC + c2] = acc + bias;
    }

    // ---------------- reset for next graph replay ----------------
    __syncthreads();
    if (tid == 0) {
        unsigned int f = atomicAdd(&g_fin, 1u);
        if (f == FIN_BLOCKS - 1) {   // last finale block; everyone else is done
            g_fin  = 0u;
            g_flag = 0u;
            g_done = 0u;
            __threadfence();
        }
    }
}

// ---------------------------------------------------------------------------
// Inputs (metadata order):
//   0: x        (32,12,128)   f32
//   1: W_heads  (8,128,64)    f32
//   2: a1_heads (8,64)        f32   (unused: softmax over identical rows is uniform)
//   3: a2_heads (8,64)        f32   (unused)
//   4: W_out    (512,64)      f32
//   5: a1_out   (64)          f32   (unused)
//   6: a2_out   (64)          f32   (unused)
//   7: Wf       (64,32768)    f32
//   8: bf       (64)          f32
// Output: (32,64) f32
// ---------------------------------------------------------------------------
extern "C" void kernel_launch(void* const* d_in, const int* in_sizes, int n_in,
                              void* d_out, int out_size)
{
    const float* x       = (const float*)d_in[0];
    const float* W_heads = (const float*)d_in[1];
    const float* W_out   = (const float*)d_in[4];
    const float* Wf      = (const float*)d_in[7];
    const float* bf      = (const float*)d_in[8];
    float* out = (float*)d_out;

    kAll<<<TOTAL_BLOCKS, 256>>>(Wf, x, W_heads, W_out, bf, out);
}

// round 11
// speedup vs baseline: 1.5254x; 1.5254x over previous
#include <cuda_runtime.h>
#include <math.h>

// Problem constants
#define NB 32     // batch
#define SS 12     // seq len
#define FF 128    // features
#define KH 8      // heads
#define HH 64     // head dim
#define CC 64     // out channels
#define NN 512    // nodes

// Scratch (no allocations allowed)
__device__ float g_v[NB * CC];   // per-batch feature vector v[b][c]

// ---------------------------------------------------------------------------
// K1 (PDL primary, tiny): per-batch features. Grid = 32 blocks x 256 threads.
// v[b][c] = sum_j elu( x_last[b] . W_heads[:,:,j] ) * W_out[j][c]
// (R7 feature math verbatim — measured fast path.)
// ---------------------------------------------------------------------------
__global__ void __launch_bounds__(256) k1_features(
    const float* __restrict__ x,
    const float* __restrict__ W_heads,
    const float* __restrict__ W_out)
{
    __shared__ __align__(16) float sbuf[128 + 2048 + 512 + 256];
    int b = blockIdx.x;
    int tid = threadIdx.x;

    float* xl    = sbuf;                 // 128
    float* hpart = sbuf + 128;           // [4 fparts][512 j]
    float* hp    = sbuf + 128 + 2048;    // 512
    float* red   = sbuf + 128 + 2048 + 512; // 256

    if (tid < 32)
        ((float4*)xl)[tid] = ((const float4*)(x + b * SS * FF + (SS - 1) * FF))[tid];
    __syncthreads();

    // hp partials: 512 slots = 4 f-partitions x 128 j-quads, 2 slots/thread
    #pragma unroll
    for (int s = 0; s < 2; ++s) {
        int slot  = tid + s * 256;       // 0..511
        int fpart = slot >> 7;           // 0..3
        int jq    = slot & 127;          // j-quad, j0 = jq*4
        int k     = jq >> 4;             // head index
        int h0    = (jq & 15) * 4;
        const float4* w = (const float4*)(W_heads + (size_t)k * FF * HH + h0);
        int f0 = fpart * 32;
        float4 acc = make_float4(0.f, 0.f, 0.f, 0.f);
        #pragma unroll 8
        for (int i = 0; i < 32; ++i) {
            float4 wv = w[(f0 + i) * 16];    // 64 floats per f-row = 16 float4
            float xv = xl[f0 + i];           // warp-broadcast
            acc.x = fmaf(xv, wv.x, acc.x);
            acc.y = fmaf(xv, wv.y, acc.y);
            acc.z = fmaf(xv, wv.z, acc.z);
            acc.w = fmaf(xv, wv.w, acc.w);
        }
        ((float4*)hpart)[fpart * 128 + jq] = acc;
    }
    __syncthreads();

    // reduce f-partitions + elu
    #pragma unroll
    for (int s = 0; s < 2; ++s) {
        int j = tid + s * 256;
        float sum = (hpart[j] + hpart[512 + j]) + (hpart[1024 + j] + hpart[1536 + j]);
        hp[j] = (sum > 0.f) ? sum : expm1f(sum);   // elu (alpha=1)
    }
    __syncthreads();

    // v[c] = sum_j hp[j]*W_out[j][c]; 4 j-parts, 2 independent chains each
    {
        int c = tid & 63;
        int part = tid >> 6;
        int j0 = part * 128;
        float acc0 = 0.f, acc1 = 0.f;
        #pragma unroll 16
        for (int j = 0; j < 64; ++j) {
            acc0 = fmaf(hp[j0 + j],      W_out[(j0 + j) * CC + c],      acc0);
            acc1 = fmaf(hp[j0 + 64 + j], W_out[(j0 + 64 + j) * CC + c], acc1);
        }
        red[part * 64 + c] = acc0 + acc1;
    }
    __syncthreads();
    #pragma unroll
    for (int s = 2; s >= 1; s >>= 1) {
        int c = tid & 63;
        int part = tid >> 6;
        if (part < s) red[part * 64 + c] += red[(part + s) * 64 + c];
        __syncthreads();
    }
    if (tid < CC) g_v[b * CC + tid] = red[tid];
}

// ---------------------------------------------------------------------------
// K2 (PDL secondary, big): stream + finale. Grid = 64 blocks (c2) x 512 threads.
// Phase A (independent of K1): Wfsum[c] = sum_n Wf[c2][n*64+c]   (128 KB/block)
// cudaGridDependencySynchronize()
// Phase B: out[b][c2] = bf[c2] + dot(v[b], Wfsum)
// ---------------------------------------------------------------------------
__global__ void __launch_bounds__(512) k2_stream_final(
    const float* __restrict__ Wf,
    const float* __restrict__ bf,
    float* __restrict__ out)
{
    __shared__ __align__(16) float4 sred[32 * 16];   // [group][lane] 8 KB
    __shared__ __align__(16) float4 sv4[NB * 16];    // all v, 8 KB
    __shared__ __align__(16) float4 sw4[16];         // Wfsum row

    int c2  = blockIdx.x;
    int tid = threadIdx.x;
    int lane = tid & 15;          // float4 index within 64-float row
    int g    = tid >> 4;          // 0..31 n-groups

    // ---- Phase A: stream this c2's Wf row (no dependency on K1) ----
    const float4* base = (const float4*)(Wf + (size_t)c2 * (NN * CC));

    // 16 independent loads/thread: n = g, g+32, ..., g+480
    float4 acc = make_float4(0.f, 0.f, 0.f, 0.f);
    #pragma unroll
    for (int i = 0; i < 16; ++i) {
        float4 t = base[(size_t)(g + 32 * i) * 16 + lane];
        acc.x += t.x; acc.y += t.y; acc.z += t.z; acc.w += t.w;
    }
    sred[g * 16 + lane] = acc;
    __syncthreads();

    // tree-reduce over 32 groups (deterministic)
    #pragma unroll
    for (int s = 16; s >= 1; s >>= 1) {
        if (g < s) {
            float4 o = sred[(g + s) * 16 + lane];
            float4 m = sred[g * 16 + lane];
            m.x += o.x; m.y += o.y; m.z += o.z; m.w += o.w;
            sred[g * 16 + lane] = m;
        }
        __syncthreads();
    }
    if (tid < 16) sw4[tid] = sred[tid];

    // ---- wait for K1 (features) to complete ----
    cudaGridDependencySynchronize();

    // load all v (512 float4, 1/thread) + bias
    sv4[tid] = ((const float4*)g_v)[tid];
    float bias = bf[c2];          // warp-broadcast
    __syncthreads();

    // out[b][c2]: tid -> b = tid/16, part = tid%16 (4 c's each), shuffle-reduce
    {
        int b = tid >> 4;         // 0..31
        int part = tid & 15;
        float4 a = sv4[b * 16 + part];
        float4 w = sw4[part];     // broadcast within half-warp
        float acc2 = fmaf(a.x, w.x, fmaf(a.y, w.y, fmaf(a.z, w.z, a.w * w.w)));
        acc2 += __shfl_xor_sync(0xffffffffu, acc2, 1);
        acc2 += __shfl_xor_sync(0xffffffffu, acc2, 2);
        acc2 += __shfl_xor_sync(0xffffffffu, acc2, 4);
        acc2 += __shfl_xor_sync(0xffffffffu, acc2, 8);
        if (part == 0)
            out[b * CC + c2] = acc2 + bias;
    }
}

// ---------------------------------------------------------------------------
// Inputs (metadata order):
//   0: x        (32,12,128)   f32
//   1: W_heads  (8,128,64)    f32
//   2: a1_heads (8,64)        f32   (unused: softmax over identical rows is uniform)
//   3: a2_heads (8,64)        f32   (unused)
//   4: W_out    (512,64)      f32
//   5: a1_out   (64)          f32   (unused)
//   6: a2_out   (64)          f32   (unused)
//   7: Wf       (64,32768)    f32
//   8: bf       (64)          f32
// Output: (32,64) f32
// ---------------------------------------------------------------------------
extern "C" void kernel_launch(void* const* d_in, const int* in_sizes, int n_in,
                              void* d_out, int out_size)
{
    const float* x       = (const float*)d_in[0];
    const float* W_heads = (const float*)d_in[1];
    const float* W_out   = (const float*)d_in[4];
    const float* Wf      = (const float*)d_in[7];
    const float* bf      = (const float*)d_in[8];
    float* out = (float*)d_out;

    // K1: tiny primary (32 blocks) — leaves the chip free for K2 placement.
    k1_features<<<NB, 256>>>(x, W_heads, W_out);

    // K2: PDL secondary — launches & streams Wf while K1 runs; only the
    // final dot is gated on K1 completion (cudaGridDependencySynchronize).
    cudaLaunchConfig_t cfg = {};
    cfg.gridDim = dim3(CC);
    cfg.blockDim = dim3(512);
    cfg.dynamicSmemBytes = 0;
    cfg.stream = 0;
    cudaLaunchAttribute attrs[1];
    attrs[0].id = cudaLaunchAttributeProgrammaticStreamSerialization;
    attrs[0].val.programmaticStreamSerializationAllowed = 1;
    cfg.attrs = attrs;
    cfg.numAttrs = 1;
    cudaLaunchKernelEx(&cfg, k2_stream_final, Wf, bf, out);
}

// round 12
// speedup vs baseline: 1.5551x; 1.0194x over previous
#include <cuda_runtime.h>
#include <math.h>

// Problem constants
#define NB 32     // batch
#define SS 12     // seq len
#define FF 128    // features
#define KH 8      // heads
#define HH 64     // head dim
#define CC 64     // out channels
#define NN 512    // nodes

#define CLUSTER 4                 // CTAs per c2 (n-quarters)
#define K2_BLOCKS (CC * CLUSTER)  // 256

// Scratch (no allocations allowed)
__device__ float g_v[NB * CC];   // per-batch feature vector v[b][c]

// ---------------------------------------------------------------------------
// K1 (PDL primary, tiny): per-batch features. Grid = 32 blocks x 256 threads.
// v[b][c] = sum_j elu( x_last[b] . W_heads[:,:,j] ) * W_out[j][c]
// ---------------------------------------------------------------------------
__global__ void __launch_bounds__(256) k1_features(
    const float* __restrict__ x,
    const float* __restrict__ W_heads,
    const float* __restrict__ W_out)
{
    __shared__ __align__(16) float sbuf[128 + 2048 + 512 + 256];
    int b = blockIdx.x;
    int tid = threadIdx.x;

    float* xl    = sbuf;                 // 128
    float* hpart = sbuf + 128;           // [4 fparts][512 j]
    float* hp    = sbuf + 128 + 2048;    // 512
    float* red   = sbuf + 128 + 2048 + 512; // 256

    if (tid < 32)
        ((float4*)xl)[tid] = ((const float4*)(x + b * SS * FF + (SS - 1) * FF))[tid];
    __syncthreads();

    #pragma unroll
    for (int s = 0; s < 2; ++s) {
        int slot  = tid + s * 256;       // 0..511
        int fpart = slot >> 7;           // 0..3
        int jq    = slot & 127;          // j-quad
        int k     = jq >> 4;             // head index
        int h0    = (jq & 15) * 4;
        const float4* w = (const float4*)(W_heads + (size_t)k * FF * HH + h0);
        int f0 = fpart * 32;
        float4 acc = make_float4(0.f, 0.f, 0.f, 0.f);
        #pragma unroll 8
        for (int i = 0; i < 32; ++i) {
            float4 wv = w[(f0 + i) * 16];
            float xv = xl[f0 + i];
            acc.x = fmaf(xv, wv.x, acc.x);
            acc.y = fmaf(xv, wv.y, acc.y);
            acc.z = fmaf(xv, wv.z, acc.z);
            acc.w = fmaf(xv, wv.w, acc.w);
        }
        ((float4*)hpart)[fpart * 128 + jq] = acc;
    }
    __syncthreads();

    #pragma unroll
    for (int s = 0; s < 2; ++s) {
        int j = tid + s * 256;
        float sum = (hpart[j] + hpart[512 + j]) + (hpart[1024 + j] + hpart[1536 + j]);
        hp[j] = (sum > 0.f) ? sum : expm1f(sum);   // elu (alpha=1)
    }
    __syncthreads();

    {
        int c = tid & 63;
        int part = tid >> 6;
        int j0 = part * 128;
        float acc0 = 0.f, acc1 = 0.f;
        #pragma unroll 16
        for (int j = 0; j < 64; ++j) {
            acc0 = fmaf(hp[j0 + j],      W_out[(j0 + j) * CC + c],      acc0);
            acc1 = fmaf(hp[j0 + 64 + j], W_out[(j0 + 64 + j) * CC + c], acc1);
        }
        red[part * 64 + c] = acc0 + acc1;
    }
    __syncthreads();
    #pragma unroll
    for (int s = 2; s >= 1; s >>= 1) {
        int c = tid & 63;
        int part = tid >> 6;
        if (part < s) red[part * 64 + c] += red[(part + s) * 64 + c];
        __syncthreads();
    }
    if (tid < CC) g_v[b * CC + tid] = red[tid];
}

// ---------------------------------------------------------------------------
// K2 (PDL secondary): stream + finale. Grid = 256 blocks = 64 clusters of 4.
// Each CTA streams a 32 KB n-quarter of its c2's Wf row (8 front-batched
// float4/thread); quarters combine in the leader's SMEM via DSMEM; leader
// waits on K1 (PDL) and emits out[*][c2].
// ---------------------------------------------------------------------------
__global__ void __launch_bounds__(256, 2) __cluster_dims__(CLUSTER, 1, 1)
k2_stream_final(
    const float* __restrict__ Wf,
    const float* __restrict__ bf,
    float* __restrict__ out)
{
    __shared__ __align__(16) float4 sred[16 * 16];       // intra-CTA reduce
    __shared__ __align__(16) float4 slot4[CLUSTER * 16]; // cluster gather (leader's used)
    __shared__ __align__(16) float4 sv4[NB * 16];        // all v (leader only)
    __shared__ __align__(16) float4 sw4[16];             // final Wfsum row

    int bid  = blockIdx.x;
    int c2   = bid >> 2;
    int tid  = threadIdx.x;
    int lane = tid & 15;          // float4 index within 64-float row
    int g    = tid >> 4;          // 0..15 row-groups

    unsigned int rank;
    asm("mov.u32 %0, %%cluster_ctarank;" : "=r"(rank));

    // ---- Phase A: stream this CTA's quarter (128 rows of 64 floats) ----
    const float4* base = (const float4*)(Wf + (size_t)c2 * (NN * CC))
                         + (size_t)rank * 128 * 16;

    int n0 = g * 8;
    float4 v0 = base[(n0 + 0) * 16 + lane];
    float4 v1 = base[(n0 + 1) * 16 + lane];
    float4 v2 = base[(n0 + 2) * 16 + lane];
    float4 v3 = base[(n0 + 3) * 16 + lane];
    float4 v4 = base[(n0 + 4) * 16 + lane];
    float4 v5 = base[(n0 + 5) * 16 + lane];
    float4 v6 = base[(n0 + 6) * 16 + lane];
    float4 v7 = base[(n0 + 7) * 16 + lane];
    float4 acc;
    acc.x = ((v0.x + v1.x) + (v2.x + v3.x)) + ((v4.x + v5.x) + (v6.x + v7.x));
    acc.y = ((v0.y + v1.y) + (v2.y + v3.y)) + ((v4.y + v5.y) + (v6.y + v7.y));
    acc.z = ((v0.z + v1.z) + (v2.z + v3.z)) + ((v4.z + v5.z) + (v6.z + v7.z));
    acc.w = ((v0.w + v1.w) + (v2.w + v3.w)) + ((v4.w + v5.w) + (v6.w + v7.w));
    sred[g * 16 + lane] = acc;
    __syncthreads();

    #pragma unroll
    for (int s = 8; s >= 1; s >>= 1) {
        if (g < s) {
            float4 o = sred[(g + s) * 16 + lane];
            float4 m = sred[g * 16 + lane];
            m.x += o.x; m.y += o.y; m.z += o.z; m.w += o.w;
            sred[g * 16 + lane] = m;
        }
        __syncthreads();
    }

    // ---- push this CTA's 64-float partial row into leader's slot[rank] ----
    if (tid < 64) {
        const float* sredf = (const float*)sred;          // row = sredf[0..63]
        float* slotf = (float*)slot4;
        unsigned int laddr = (unsigned int)__cvta_generic_to_shared(
                                &slotf[rank * 64 + tid]);
        unsigned int raddr;
        asm("mapa.shared::cluster.u32 %0, %1, %2;"
            : "=r"(raddr) : "r"(laddr), "r"(0u));
        asm volatile("st.shared::cluster.f32 [%0], %1;"
                     :: "r"(raddr), "f"(sredf[tid]) : "memory");
    }

    asm volatile("barrier.cluster.arrive.aligned;" ::: "memory");
    asm volatile("barrier.cluster.wait.aligned;" ::: "memory");

    if (rank != 0) return;

    // ---- leader: combine 4 quarter-rows ----
    if (tid < 16) {
        float4 a0 = slot4[0 * 16 + tid];
        float4 a1 = slot4[1 * 16 + tid];
        float4 a2 = slot4[2 * 16 + tid];
        float4 a3 = slot4[3 * 16 + tid];
        float4 s;
        s.x = (a0.x + a1.x) + (a2.x + a3.x);
        s.y = (a0.y + a1.y) + (a2.y + a3.y);
        s.z = (a0.z + a1.z) + (a2.z + a3.z);
        s.w = (a0.w + a1.w) + (a2.w + a3.w);
        sw4[tid] = s;
    }

    // ---- wait for K1 (features), then finale ----
    cudaGridDependencySynchronize();

    sv4[tid]       = ((const float4*)g_v)[tid];
    sv4[tid + 256] = ((const float4*)g_v)[tid + 256];
    float bias = bf[c2];
    __syncthreads();

    // out[b][c2]: tid -> b = tid/8, part = tid%8 (2 float4 each), shuffle-reduce
    {
        int b = tid >> 3;             // 0..31
        int part = tid & 7;
        float4 a0 = sv4[b * 16 + part * 2 + 0];
        float4 a1 = sv4[b * 16 + part * 2 + 1];
        float4 w0 = sw4[part * 2 + 0];
        float4 w1 = sw4[part * 2 + 1];
        float acc2 = fmaf(a0.x, w0.x, fmaf(a0.y, w0.y, fmaf(a0.z, w0.z, a0.w * w0.w)));
        acc2 = fmaf(a1.x, w1.x, fmaf(a1.y, w1.y, fmaf(a1.z, w1.z, fmaf(a1.w, w1.w, acc2))));
        acc2 += __shfl_xor_sync(0xffffffffu, acc2, 1);
        acc2 += __shfl_xor_sync(0xffffffffu, acc2, 2);
        acc2 += __shfl_xor_sync(0xffffffffu, acc2, 4);
        if (part == 0)
            out[b * CC + c2] = acc2 + bias;
    }
}

// ---------------------------------------------------------------------------
// Inputs (metadata order):
//   0: x        (32,12,128)   f32
//   1: W_heads  (8,128,64)    f32
//   2: a1_heads (8,64)        f32   (unused: softmax over identical rows is uniform)
//   3: a2_heads (8,64)        f32   (unused)
//   4: W_out    (512,64)      f32
//   5: a1_out   (64)          f32   (unused)
//   6: a2_out   (64)          f32   (unused)
//   7: Wf       (64,32768)    f32
//   8: bf       (64)          f32
// Output: (32,64) f32
// ---------------------------------------------------------------------------
extern "C" void kernel_launch(void* const* d_in, const int* in_sizes, int n_in,
                              void* d_out, int out_size)
{
    const float* x       = (const float*)d_in[0];
    const float* W_heads = (const float*)d_in[1];
    const float* W_out   = (const float*)d_in[4];
    const float* Wf      = (const float*)d_in[7];
    const float* bf      = (const float*)d_in[8];
    float* out = (float*)d_out;

    // K1: tiny primary (32 blocks) — leaves the chip free for K2 placement.
    k1_features<<<NB, 256>>>(x, W_heads, W_out);

    // K2: PDL secondary with cluster dims from __cluster_dims__.
    cudaLaunchConfig_t cfg = {};
    cfg.gridDim = dim3(K2_BLOCKS);
    cfg.blockDim = dim3(256);
    cfg.dynamicSmemBytes = 0;
    cfg.stream = 0;
    cudaLaunchAttribute attrs[1];
    attrs[0].id = cudaLaunchAttributeProgrammaticStreamSerialization;
    attrs[0].val.programmaticStreamSerializationAllowed = 1;
    cfg.attrs = attrs;
    cfg.numAttrs = 1;
    cudaLaunchKernelEx(&cfg, k2_stream_final, Wf, bf, out);
}